// round 10
// baseline (speedup 1.0000x reference)
#include <cuda_runtime.h>

typedef unsigned long long u64;

static constexpr int TPB        = 128;
static constexpr int TILE_PAIRS = 128;             // row-pairs per tile (= TPB)
static constexpr int TILE_BYTES = TILE_PAIRS * 80; // 10240 (pair = 2 rows * 40B)
static constexpr int MAX_GRID   = 1184;            // 8 blocks/SM persistent

// Weights in constant memory: warp-uniform, loop-invariant -> LDCU path,
// zero registers, zero smem/LSU traffic. Raw-float layout matches the device
// arrays so kernel_launch can memcpy them straight in (D2D, graph-capturable).
__constant__ ulonglong2 cW1[10][4];   // [i][j] = W1[i][4j..4j+3] as 2 packed f32 pairs
__constant__ ulonglong2 cB1[4];       // b1 as 8 packed pairs
__constant__ ulonglong2 cW2[4];       // W2 as 8 packed pairs
__constant__ float      cB2[1];
__constant__ float      cThr[1];

// ---- packed f32x2 helpers (ptxas only emits FFMA2 from PTX fma.rn.f32x2) ----
__device__ __forceinline__ u64 pk(float lo, float hi) {
    u64 r; asm("mov.b64 %0, {%1, %2};" : "=l"(r) : "f"(lo), "f"(hi)); return r;
}
__device__ __forceinline__ float2 upk(u64 v) {
    float2 f; asm("mov.b64 {%0, %1}, %2;" : "=f"(f.x), "=f"(f.y) : "l"(v)); return f;
}
__device__ __forceinline__ u64 fma2(u64 a, u64 b, u64 c) {
    u64 d; asm("fma.rn.f32x2 %0, %1, %2, %3;" : "=l"(d) : "l"(a), "l"(b), "l"(c)); return d;
}
__device__ __forceinline__ unsigned s2u(const void* p) {
    unsigned a;
    asm("{ .reg .u64 t; cvta.to.shared.u64 t, %1; cvt.u32.u64 %0, t; }" : "=r"(a) : "l"(p));
    return a;
}
__device__ __forceinline__ void cp16(unsigned dst, const void* src, int pred) {
    asm volatile("{ .reg .pred p; setp.ne.b32 p, %2, 0;"
                 " @p cp.async.cg.shared.global [%0], [%1], 16; }"
                 :: "r"(dst), "l"(src), "r"(pred));
}
__device__ __forceinline__ void cpcommit() {
    asm volatile("cp.async.commit_group;" ::: "memory");
}
template<int N> __device__ __forceinline__ void cpwait() {
    asm volatile("cp.async.wait_group %0;" :: "n"(N) : "memory");
}

__global__ __launch_bounds__(TPB, 8) void mlp_threshold_kernel(
    const float* __restrict__ x,
    float* __restrict__ out,        // [B] (reversed order)
    int B, int pairs, int ntiles)
{
    __shared__ float4 sx[2][TILE_BYTES / 16];       // 16B-aligned x staging

    const int t = threadIdx.x;

    const char* xb = (const char*)x;
    const long long total_chunks = (long long)pairs * 5;  // 16B chunks of x

    auto stage = [&](int buf, int tile) {
        unsigned sdst = s2u(&sx[buf][0]);
        long long c0 = (long long)tile * (TILE_PAIRS * 5);
        #pragma unroll
        for (int j = 0; j < 5; j++) {
            long long c = c0 + t + j * TPB;       // consecutive t -> consecutive 16B
            cp16(sdst + (unsigned)(t + j * TPB) * 16u, xb + c * 16, (int)(c < total_chunks));
        }
    };

    int tile = blockIdx.x;
    if (tile < ntiles) stage(0, tile);
    cpcommit();

    const float bb = cB2[0], tt = cThr[0];

    int cur = 0;
    for (; tile < ntiles; tile += gridDim.x) {
        int nxt = tile + gridDim.x;
        bool more = (nxt < ntiles);
        if (more) stage(cur ^ 1, nxt);
        cpcommit();
        if (more) cpwait<1>(); else cpwait<0>();
        __syncthreads();

        // ---- pair q = rows (2q, 2q+1); 80B = 5 float4, conflict-free LDS.128 ----
        int q = tile * TILE_PAIRS + t;
        bool active = (q < pairs);

        float xa[10], xbv[10];
        {
            const float4* f4 = &sx[cur][t * 5];
            float4 v0 = f4[0], v1 = f4[1], v2 = f4[2], v3 = f4[3], v4 = f4[4];
            xa[0]=v0.x; xa[1]=v0.y; xa[2]=v0.z; xa[3]=v0.w;
            xa[4]=v1.x; xa[5]=v1.y; xa[6]=v1.z; xa[7]=v1.w;
            xa[8]=v2.x; xa[9]=v2.y;
            xbv[0]=v2.z; xbv[1]=v2.w;
            xbv[2]=v3.x; xbv[3]=v3.y; xbv[4]=v3.z; xbv[5]=v3.w;
            xbv[6]=v4.x; xbv[7]=v4.y; xbv[8]=v4.z; xbv[9]=v4.w;
        }

        // acc index p = neuron pair (2p, 2p+1), p = 0..7
        u64 acc0[8], acc1[8];
        #pragma unroll
        for (int j = 0; j < 4; j++) {
            ulonglong2 bv = cB1[j];
            acc0[2*j] = bv.x; acc0[2*j+1] = bv.y;
            acc1[2*j] = bv.x; acc1[2*j+1] = bv.y;
        }

        #pragma unroll
        for (int i = 0; i < 10; i++) {
            u64 xp0 = pk(xa[i], xa[i]);
            u64 xp1 = pk(xbv[i], xbv[i]);
            #pragma unroll
            for (int j = 0; j < 4; j++) {
                ulonglong2 w = cW1[i][j];   // LDC(U).128, imm offset: neurons 4j..4j+3
                acc0[2*j]   = fma2(xp0, w.x, acc0[2*j]);
                acc1[2*j]   = fma2(xp1, w.x, acc1[2*j]);
                acc0[2*j+1] = fma2(xp0, w.y, acc0[2*j+1]);
                acc1[2*j+1] = fma2(xp1, w.y, acc1[2*j+1]);
            }
        }

        // relu + fc2 (packed dot with W2)
        u64 y0 = 0ull, y1 = 0ull;
        #pragma unroll
        for (int j = 0; j < 4; j++) {
            ulonglong2 wv = cW2[j];
            float2 h0, h1;
            h0 = upk(acc0[2*j]);   h1 = upk(acc1[2*j]);
            y0 = fma2(pk(fmaxf(h0.x,0.f), fmaxf(h0.y,0.f)), wv.x, y0);
            y1 = fma2(pk(fmaxf(h1.x,0.f), fmaxf(h1.y,0.f)), wv.x, y1);
            h0 = upk(acc0[2*j+1]); h1 = upk(acc1[2*j+1]);
            y0 = fma2(pk(fmaxf(h0.x,0.f), fmaxf(h0.y,0.f)), wv.y, y0);
            y1 = fma2(pk(fmaxf(h1.x,0.f), fmaxf(h1.y,0.f)), wv.y, y1);
        }
        float2 s0 = upk(y0), s1 = upk(y1);
        float ya = fmaxf(s0.x + s0.y + bb, 0.0f);   // row 2q
        float yb = fmaxf(s1.x + s1.y + bb, 0.0f);   // row 2q+1

        // y >= 0 so trunc == floor; jnp.round == rint (half-to-even).
        float fa = floorf(ya); float oa = (ya - fa > tt) ? rintf(ya) : fa;
        float fb = floorf(yb); float ob = (yb - fb > tt) ? rintf(yb) : fb;

        if (active) {
            float2 o; o.x = ob; o.y = oa;           // out[B-2-2q], out[B-1-2q]
            *reinterpret_cast<float2*>(out + (B - 2 - 2 * q)) = o;
        }
        __syncthreads();
        cur ^= 1;
    }

    // odd-B tail (B is even in practice): weights read from constant
    if ((B & 1) && blockIdx.x == 0 && threadIdx.x == 0) {
        int r = B - 1;
        const float* w1f = (const float*)&cW1[0][0];
        const float* b1f = (const float*)&cB1[0];
        const float* w2f = (const float*)&cW2[0];
        float h[16];
        #pragma unroll
        for (int n = 0; n < 16; n++) h[n] = b1f[n];
        for (int i = 0; i < 10; i++) {
            float xv = x[(size_t)r * 10 + i];
            #pragma unroll
            for (int n = 0; n < 16; n++) h[n] = fmaf(xv, w1f[i * 16 + n], h[n]);
        }
        float y = bb;
        #pragma unroll
        for (int n = 0; n < 16; n++) y = fmaf(fmaxf(h[n], 0.0f), w2f[n], y);
        y = fmaxf(y, 0.0f);
        float fy = floorf(y);
        out[0] = (y - fy > tt) ? rintf(y) : fy;
    }
}

extern "C" void kernel_launch(void* const* d_in, const int* in_sizes, int n_in,
                              void* d_out, int out_size) {
    const float* x   = (const float*)d_in[0];
    const float* W1  = (const float*)d_in[1];
    const float* b1  = (const float*)d_in[2];
    const float* W2  = (const float*)d_in[3];
    const float* b2  = (const float*)d_in[4];
    const float* thr = (const float*)d_in[5];
    float* out = (float*)d_out;

    // Stage weights into constant memory (D2D async memcpys: graph-capturable,
    // no allocation). Raw float layout matches the packed-pair interpretation.
    cudaMemcpyToSymbolAsync(cW1, W1, 10 * 16 * sizeof(float), 0, cudaMemcpyDeviceToDevice, 0);
    cudaMemcpyToSymbolAsync(cB1, b1, 16 * sizeof(float),      0, cudaMemcpyDeviceToDevice, 0);
    cudaMemcpyToSymbolAsync(cW2, W2, 16 * sizeof(float),      0, cudaMemcpyDeviceToDevice, 0);
    cudaMemcpyToSymbolAsync(cB2, b2, sizeof(float),           0, cudaMemcpyDeviceToDevice, 0);
    cudaMemcpyToSymbolAsync(cThr, thr, sizeof(float),         0, cudaMemcpyDeviceToDevice, 0);

    int B = out_size;
    int pairs = B >> 1;
    int ntiles = (pairs + TILE_PAIRS - 1) / TILE_PAIRS;
    int grid = ntiles < MAX_GRID ? (ntiles > 0 ? ntiles : 1) : MAX_GRID;
    mlp_threshold_kernel<<<grid, TPB>>>(x, out, B, pairs, ntiles);
}